// round 3
// baseline (speedup 1.0000x reference)
#include <cuda_runtime.h>

#define SEQ 2048
#define NB 2
#define NH 16
#define AD 64
#define DM 1024
#define BH (NB*NH)
#define NPE 33

// Scratch (device globals — no allocation allowed)
__device__ float g_Q[(size_t)BH*SEQ*AD];      // head-major Q  [bh][s][64]
__device__ float g_K[(size_t)BH*SEQ*AD];
__device__ float g_V[(size_t)BH*SEQ*AD];
__device__ float g_P[(size_t)BH*SEQ*NPE];     // rel-bias projections
__device__ float g_S[(size_t)BH*SEQ*SEQ];     // scores / probs (512 MB)
__device__ float g_C[(size_t)NB*SEQ*DM];      // context, bqhd layout

// ---------------------------------------------------------------------------
// Generic tiled fp32 GEMM.  A row-major [M,K].  B row-major [K,N] (BT=false)
// or [N,K] (BT=true, computes A·Bᵀ).  Batched over blockIdx.z via strides.
// EPI: 0 = plain C[m*N+n]
//      1 = projection scatter -> head-major [b][h][s][d]   (m=b*S+s, n=h*64+d)
//      2 = scores: += relbias, *1/8, C += z*sC, Prel += z*SEQ*NPE
//      3 = ctx scatter -> [b][q][h][d]                      (z=b*H+h, n=d)
// ---------------------------------------------------------------------------
template<int BM,int BN,int BK,int TM,int TN,bool BT,int EPI>
__global__ __launch_bounds__((BM/TM)*(BN/TN))
void gemm_k(const float* __restrict__ A, const float* __restrict__ Bm,
            float* __restrict__ C, const float* __restrict__ Prel,
            int M, int N, int K, long sA, long sB, long sC)
{
    constexpr int THREADS = (BM/TM)*(BN/TN);
    __shared__ float As[BK][BM];
    __shared__ float Bs[BK][BN];

    const int z = blockIdx.z;
    A += (long)z * sA;
    Bm += (long)z * sB;
    C += (long)z * sC;

    const int tid = threadIdx.x;
    const int tx  = tid % (BN/TN);
    const int ty  = tid / (BN/TN);
    const int bm  = blockIdx.y * BM;
    const int bn  = blockIdx.x * BN;

    float acc[TM][TN] = {};

    for (int k0 = 0; k0 < K; k0 += BK) {
        // load A tile (transposed into As[k][m])
        #pragma unroll 1
        for (int i = tid; i < BM*BK/4; i += THREADS) {
            int r = i / (BK/4);
            int c = (i % (BK/4)) * 4;
            float4 v = *reinterpret_cast<const float4*>(A + (long)(bm + r)*K + k0 + c);
            As[c+0][r] = v.x; As[c+1][r] = v.y; As[c+2][r] = v.z; As[c+3][r] = v.w;
        }
        if constexpr (BT) {
            #pragma unroll 1
            for (int i = tid; i < BN*BK/4; i += THREADS) {
                int r = i / (BK/4);
                int c = (i % (BK/4)) * 4;
                float4 v = *reinterpret_cast<const float4*>(Bm + (long)(bn + r)*K + k0 + c);
                Bs[c+0][r] = v.x; Bs[c+1][r] = v.y; Bs[c+2][r] = v.z; Bs[c+3][r] = v.w;
            }
        } else {
            #pragma unroll 1
            for (int i = tid; i < BK*BN/4; i += THREADS) {
                int r = i / (BN/4);
                int c = (i % (BN/4)) * 4;
                *reinterpret_cast<float4*>(&Bs[r][c]) =
                    *reinterpret_cast<const float4*>(Bm + (long)(k0 + r)*N + bn + c);
            }
        }
        __syncthreads();

        #pragma unroll
        for (int kk = 0; kk < BK; kk++) {
            float af[TM], bf[TN];
            #pragma unroll
            for (int i = 0; i < TM; i++) af[i] = As[kk][ty*TM + i];
            #pragma unroll
            for (int j = 0; j < TN; j++) bf[j] = Bs[kk][tx*TN + j];
            #pragma unroll
            for (int i = 0; i < TM; i++)
                #pragma unroll
                for (int j = 0; j < TN; j++)
                    acc[i][j] += af[i] * bf[j];
        }
        __syncthreads();
    }

    // epilogue
    const float* Pz = (EPI == 2) ? (Prel + (long)z * SEQ * NPE) : Prel;
    #pragma unroll
    for (int i = 0; i < TM; i++) {
        const int m = bm + ty*TM + i;
        #pragma unroll
        for (int j = 0; j < TN; j++) {
            const int n = bn + tx*TN + j;
            float v = acc[i][j];
            if constexpr (EPI == 0) {
                C[(long)m * N + n] = v;
            } else if constexpr (EPI == 1) {
                int b = m / SEQ, s = m % SEQ;
                int h = n / AD,  d = n % AD;
                C[(((long)(b*NH + h))*SEQ + s)*AD + d] = v;
            } else if constexpr (EPI == 2) {
                int rel = n - m;
                rel = rel < -16 ? -16 : (rel > 16 ? 16 : rel);
                v = (v + Pz[m*NPE + rel + 16]) * 0.125f;
                C[(long)m * N + n] = v;
            } else { // EPI == 3
                int b = z / NH, h = z % NH;
                C[(((long)b*SEQ + m)*NH + h)*AD + n] = v;
            }
        }
    }
}

// Prel[bh*S+q][j] = dot(Qh[bh][q][:], rel_pemb[j][:])  for j in 0..32
__global__ __launch_bounds__(64)
void relproj_k(const float* __restrict__ Q, const float* __restrict__ pemb,
               float* __restrict__ P)
{
    __shared__ float qs[AD];
    const long row = blockIdx.x;
    qs[threadIdx.x] = Q[row*AD + threadIdx.x];
    __syncthreads();
    const int j = threadIdx.x;
    if (j < NPE) {
        float s = 0.f;
        #pragma unroll
        for (int d = 0; d < AD; d++) s += qs[d] * pemb[j*AD + d];
        P[row*NPE + j] = s;
    }
}

// Row softmax over SEQ=2048 elements, one block per row, 256 threads.
__global__ __launch_bounds__(256)
void softmax_k(float* __restrict__ S)
{
    const long row = blockIdx.x;
    float4* p = reinterpret_cast<float4*>(S + row * SEQ);
    const int t = threadIdx.x;
    float4 a = p[t], b = p[t + 256];

    float m = fmaxf(fmaxf(fmaxf(a.x, a.y), fmaxf(a.z, a.w)),
                    fmaxf(fmaxf(b.x, b.y), fmaxf(b.z, b.w)));
    #pragma unroll
    for (int o = 16; o > 0; o >>= 1) m = fmaxf(m, __shfl_xor_sync(0xffffffffu, m, o));

    __shared__ float red[8];
    const int wid = t >> 5, lane = t & 31;
    if (lane == 0) red[wid] = m;
    __syncthreads();
    float gm = red[0];
    #pragma unroll
    for (int i = 1; i < 8; i++) gm = fmaxf(gm, red[i]);
    __syncthreads();

    a.x = __expf(a.x - gm); a.y = __expf(a.y - gm);
    a.z = __expf(a.z - gm); a.w = __expf(a.w - gm);
    b.x = __expf(b.x - gm); b.y = __expf(b.y - gm);
    b.z = __expf(b.z - gm); b.w = __expf(b.w - gm);

    float s = a.x + a.y + a.z + a.w + b.x + b.y + b.z + b.w;
    #pragma unroll
    for (int o = 16; o > 0; o >>= 1) s += __shfl_xor_sync(0xffffffffu, s, o);
    if (lane == 0) red[wid] = s;
    __syncthreads();
    float gs = 0.f;
    #pragma unroll
    for (int i = 0; i < 8; i++) gs += red[i];

    const float inv = 1.f / gs;
    a.x *= inv; a.y *= inv; a.z *= inv; a.w *= inv;
    b.x *= inv; b.y *= inv; b.z *= inv; b.w *= inv;
    p[t] = a; p[t + 256] = b;
}

extern "C" void kernel_launch(void* const* d_in, const int* in_sizes, int n_in,
                              void* d_out, int out_size)
{
    const float* iQ   = (const float*)d_in[0];
    const float* iK   = (const float*)d_in[1];
    const float* iV   = (const float*)d_in[2];
    const float* Wq   = (const float*)d_in[3];
    const float* Wk   = (const float*)d_in[4];
    const float* Wv   = (const float*)d_in[5];
    const float* Wo   = (const float*)d_in[6];
    const float* pemb = (const float*)d_in[7];
    float* out = (float*)d_out;

    float *Q, *K, *V, *P, *S, *C;
    cudaGetSymbolAddress((void**)&Q, g_Q);
    cudaGetSymbolAddress((void**)&K, g_K);
    cudaGetSymbolAddress((void**)&V, g_V);
    cudaGetSymbolAddress((void**)&P, g_P);
    cudaGetSymbolAddress((void**)&S, g_S);
    cudaGetSymbolAddress((void**)&C, g_C);

    // 1) Projections -> head-major [b][h][s][d]
    dim3 gproj(DM/128, (NB*SEQ)/128, 1);
    gemm_k<128,128,8,8,8,false,1><<<gproj, 256>>>(iQ, Wq, Q, nullptr, NB*SEQ, DM, DM, 0, 0, 0);
    gemm_k<128,128,8,8,8,false,1><<<gproj, 256>>>(iK, Wk, K, nullptr, NB*SEQ, DM, DM, 0, 0, 0);
    gemm_k<128,128,8,8,8,false,1><<<gproj, 256>>>(iV, Wv, V, nullptr, NB*SEQ, DM, DM, 0, 0, 0);

    // 2) Rel-position bias projections P[bh,q,33] = q . rel_pemb[j]
    relproj_k<<<BH*SEQ, 64>>>(Q, pemb, P);

    // 3) Scores = Q Kᵀ (+relbias)/8, batched over bh
    dim3 gsc(SEQ/128, SEQ/128, BH);
    gemm_k<128,128,8,8,8,true,2><<<gsc, 256>>>(Q, K, S, P, SEQ, SEQ, AD,
                                               (long)SEQ*AD, (long)SEQ*AD, (long)SEQ*SEQ);

    // 4) Softmax over last dim
    softmax_k<<<BH*SEQ, 256>>>(S);

    // 5) ctx = probs @ V  -> [b][q][h][d]
    dim3 gpv(1, SEQ/128, BH);
    gemm_k<128,64,8,8,4,false,3><<<gpv, 256>>>(S, V, C, nullptr, SEQ, AD, SEQ,
                                               (long)SEQ*SEQ, (long)SEQ*AD, 0);

    // 6) out = ctx @ Wo
    gemm_k<128,128,8,8,8,false,0><<<gproj, 256>>>(C, Wo, out, nullptr, NB*SEQ, DM, DM, 0, 0, 0);
}

// round 5
// speedup vs baseline: 1.6236x; 1.6236x over previous
#include <cuda_runtime.h>
#include <cuda_bf16.h>
#include <cstdint>

#define SEQ 2048
#define NB 2
#define NH 16
#define AD 64
#define DM 1024
#define BH (NB*NH)
#define NPE 33

// ---------------- scratch (no allocation allowed) ----------------
__device__ float g_Q[(size_t)BH*SEQ*AD];
__device__ float g_K[(size_t)BH*SEQ*AD];
__device__ float g_P[(size_t)BH*SEQ*NPE];
__device__ float g_S[(size_t)BH*SEQ*SEQ];
__device__ float g_C[(size_t)NB*SEQ*DM];
__device__ float g_Vt[(size_t)BH*AD*SEQ];    // V transposed per head: [bh][d][s]
__device__ float g_Wt[(size_t)4*DM*DM];      // Wq,Wk,Wv,Wo transposed [n][k]

// ---------------- helpers ----------------
__device__ __forceinline__ uint32_t s2u(const void* p) {
    uint32_t a;
    asm("{ .reg .u64 t; cvta.to.shared.u64 t, %1; cvt.u32.u64 %0, t; }" : "=r"(a) : "l"(p));
    return a;
}
__device__ __forceinline__ uint32_t swz(uint32_t o) { return o ^ ((o >> 3) & 0x70); }

__device__ __forceinline__ void ldsm4(uint32_t* r, uint32_t addr) {
    asm volatile("ldmatrix.sync.aligned.m8n8.x4.shared.b16 {%0,%1,%2,%3}, [%4];"
                 : "=r"(r[0]), "=r"(r[1]), "=r"(r[2]), "=r"(r[3]) : "r"(addr));
}
__device__ __forceinline__ void mma_bf16(float* d, const uint32_t* a, const uint32_t* b) {
    asm volatile("mma.sync.aligned.m16n8k16.row.col.f32.bf16.bf16.f32 "
                 "{%0,%1,%2,%3}, {%4,%5,%6,%7}, {%8,%9}, {%0,%1,%2,%3};"
                 : "+f"(d[0]), "+f"(d[1]), "+f"(d[2]), "+f"(d[3])
                 : "r"(a[0]), "r"(a[1]), "r"(a[2]), "r"(a[3]), "r"(b[0]), "r"(b[1]));
}
__device__ __forceinline__ void cvt_hl(float4 v, uint2& h2, uint2& l2) {
    float xs[4] = {v.x, v.y, v.z, v.w};
    unsigned short h[4], l[4];
    #pragma unroll
    for (int j = 0; j < 4; j++) {
        __nv_bfloat16 hb = __float2bfloat16(xs[j]);
        __nv_bfloat16 lb = __float2bfloat16(xs[j] - __bfloat162float(hb));
        h[j] = __bfloat16_as_ushort(hb);
        l[j] = __bfloat16_as_ushort(lb);
    }
    h2 = make_uint2((uint32_t)h[1] << 16 | h[0], (uint32_t)h[3] << 16 | h[2]);
    l2 = make_uint2((uint32_t)l[1] << 16 | l[0], (uint32_t)l[3] << 16 | l[2]);
}

// ---------------------------------------------------------------------------
// mma.sync split-bf16 GEMM.  D[128,BN] = A[128,K] (row, lda=K) * B[BN,K]^T (row, ldb=K)
// BK=64, SW128 smem, double buffered (NBUF=2) or single (NBUF=1).
// EPI: 0 plain [m][DM] | 1 proj->head-major | 2 scores(+bias,/8) | 3 ctx scatter
//      4 Vt scatter [bh][d][s]
// ---------------------------------------------------------------------------
template<int BN, int NBUF, int EPI>
__global__ __launch_bounds__(256)
void gemm_mma(const float* __restrict__ A, const float* __restrict__ Bm,
              float* __restrict__ C, const float* __restrict__ Pr,
              int K, long sA, long sB, long sC)
{
    extern __shared__ char dsm[];
    const uint32_t raw = s2u(dsm);
    const uint32_t sb  = (raw + 1023u) & ~1023u;
    char* sp = dsm + (sb - raw);

    constexpr int N8     = BN / 16;              // n8 tiles per warp
    constexpr int SS     = 32768 + BN * 256;     // bytes per stage (Ah+Al+Bh+Bl)
    constexpr int AOFF_L = 16384;
    constexpr int BOFF_H = 32768;
    constexpr int BOFF_L = 32768 + BN * 128;

    const int z = blockIdx.z;
    A  += (size_t)z * sA;
    Bm += (size_t)z * sB;
    C  += (size_t)z * sC;
    const int bm = blockIdx.y * 128, bn = blockIdx.x * BN;
    const int tid = threadIdx.x, wid = tid >> 5, lane = tid & 31;
    const int wm = (wid >> 1) * 32, wn = (wid & 1) * (BN / 2);

    float acc[2][N8][4];
    #pragma unroll
    for (int i = 0; i < 2; i++)
        #pragma unroll
        for (int j = 0; j < N8; j++)
            #pragma unroll
            for (int r = 0; r < 4; r++) acc[i][j][r] = 0.f;

    const int NS = K / 64;

    auto load_stage = [&](int buf, int k0) {
        {   // A tile: 128 rows x 64 cols, 2 threads/row
            const int row = tid >> 1, part = tid & 1;
            const float4* ap = reinterpret_cast<const float4*>(
                A + (size_t)(bm + row) * K + k0) + part * 8;
            char* ah = sp + buf * SS;
            char* al = ah + AOFF_L;
            const uint32_t rb = (uint32_t)row * 128u + (uint32_t)part * 64u;
            #pragma unroll
            for (int i = 0; i < 8; i++) {
                uint2 h2, l2; cvt_hl(ap[i], h2, l2);
                const uint32_t sw = swz(rb + (uint32_t)i * 8u);
                *reinterpret_cast<uint2*>(ah + sw) = h2;
                *reinterpret_cast<uint2*>(al + sw) = l2;
            }
        }
        {   // B tile: BN rows x 64 cols
            constexpr int TPR = 256 / BN;
            constexpr int F4  = 16 / TPR;
            const int row = tid / TPR, part = tid % TPR;
            const float4* bp = reinterpret_cast<const float4*>(
                Bm + (size_t)(bn + row) * K + k0) + part * F4;
            char* bh = sp + buf * SS + BOFF_H;
            char* bl = sp + buf * SS + BOFF_L;
            const uint32_t rb = (uint32_t)row * 128u + (uint32_t)(part * F4) * 8u;
            #pragma unroll
            for (int i = 0; i < F4; i++) {
                uint2 h2, l2; cvt_hl(bp[i], h2, l2);
                const uint32_t sw = swz(rb + (uint32_t)i * 8u);
                *reinterpret_cast<uint2*>(bh + sw) = h2;
                *reinterpret_cast<uint2*>(bl + sw) = l2;
            }
        }
    };

    load_stage(0, 0);
    __syncthreads();

    for (int s = 0; s < NS; s++) {
        const int b = (NBUF == 2) ? (s & 1) : 0;
        const uint32_t AhB = sb + (uint32_t)b * SS;
        const uint32_t AlB = AhB + AOFF_L;
        const uint32_t BhB = AhB + BOFF_H;
        const uint32_t BlB = AhB + BOFF_L;

        #pragma unroll
        for (int kk = 0; kk < 4; kk++) {
            const uint32_t kB = (uint32_t)kk * 32u;
            uint32_t ah[2][4], alr[2][4];
            {
                const uint32_t aoff = (((uint32_t)lane >> 4) << 4) + kB;
                #pragma unroll
                for (int mt = 0; mt < 2; mt++) {
                    const uint32_t sw = swz((uint32_t)(wm + mt * 16 + (lane & 15)) * 128u + aoff);
                    ldsm4(ah[mt],  AhB + sw);
                    ldsm4(alr[mt], AlB + sw);
                }
            }
            uint32_t bh2[N8 * 2], bl2[N8 * 2];
            {
                const uint32_t boff = ((((uint32_t)lane >> 3) & 1u) << 4) + kB;
                const uint32_t brow = (uint32_t)(wn + (lane & 7) + ((lane >> 4) << 3));
                #pragma unroll
                for (int g = 0; g < N8 / 2; g++) {
                    const uint32_t sw = swz((brow + (uint32_t)g * 16u) * 128u + boff);
                    ldsm4(&bh2[g * 4], BhB + sw);
                    ldsm4(&bl2[g * 4], BlB + sw);
                }
            }
            #pragma unroll
            for (int mt = 0; mt < 2; mt++)
                #pragma unroll
                for (int nt = 0; nt < N8; nt++) {
                    mma_bf16(acc[mt][nt], ah[mt],  &bh2[nt * 2]);
                    mma_bf16(acc[mt][nt], ah[mt],  &bl2[nt * 2]);
                    mma_bf16(acc[mt][nt], alr[mt], &bh2[nt * 2]);
                }
        }
        if (s + 1 < NS) load_stage((s + 1) & 1, (s + 1) * 64);
        __syncthreads();
    }

    float* prow = reinterpret_cast<float*>(sp);
    if constexpr (EPI == 2) {
        const float* Pz = Pr + ((size_t)z * SEQ + bm) * NPE;
        for (int j = tid; j < 128 * NPE; j += 256) prow[j] = Pz[j];
        __syncthreads();
    }

    #pragma unroll
    for (int mt = 0; mt < 2; mt++)
        #pragma unroll
        for (int nt = 0; nt < N8; nt++)
            #pragma unroll
            for (int r = 0; r < 4; r++) {
                const int m = bm + wm + mt * 16 + (lane >> 2) + ((r >> 1) << 3);
                const int n = bn + wn + nt * 8 + ((lane & 3) << 1) + (r & 1);
                const float v = acc[mt][nt][r];
                if constexpr (EPI == 0) {
                    C[(size_t)m * DM + n] = v;
                } else if constexpr (EPI == 1) {
                    const int b_ = m >> 11, s_ = m & 2047, h_ = n >> 6, d_ = n & 63;
                    C[(((size_t)(b_ * NH + h_)) * SEQ + s_) * AD + d_] = v;
                } else if constexpr (EPI == 2) {
                    int idx = n - m + 16;
                    idx = idx < 0 ? 0 : (idx > 32 ? 32 : idx);
                    C[(size_t)m * SEQ + n] = (v + prow[(m - bm) * NPE + idx]) * 0.125f;
                } else if constexpr (EPI == 3) {
                    const int b_ = z >> 4, h_ = z & 15;
                    C[(((size_t)b_ * SEQ + m) * NH + h_) * AD + n] = v;
                } else { // EPI == 4 : Vt scatter
                    const int b_ = m >> 11, s_ = m & 2047, h_ = n >> 6, d_ = n & 63;
                    C[(((size_t)(b_ * NH + h_)) * AD + d_) * SEQ + s_] = v;
                }
            }
}

// ---------------- weight transpose: Wt[n][k] = W[k][n], 4 mats ----------------
__global__ __launch_bounds__(256)
void transp_w(const float* __restrict__ W0, const float* __restrict__ W1,
              const float* __restrict__ W2, const float* __restrict__ W3,
              float* __restrict__ out)
{
    __shared__ float t[32][33];
    const float* W = (blockIdx.z == 0) ? W0 : (blockIdx.z == 1) ? W1
                   : (blockIdx.z == 2) ? W2 : W3;
    float* O = out + (size_t)blockIdx.z * DM * DM;
    const int tx = threadIdx.x & 31, ty = threadIdx.x >> 5;
    const int x = blockIdx.x * 32 + tx, y = blockIdx.y * 32 + ty;
    #pragma unroll
    for (int j = 0; j < 32; j += 8) t[ty + j][tx] = W[(size_t)(y + j) * DM + x];
    __syncthreads();
    const int xo = blockIdx.y * 32 + tx, yo = blockIdx.x * 32 + ty;
    #pragma unroll
    for (int j = 0; j < 32; j += 8) O[(size_t)(yo + j) * DM + xo] = t[tx][ty + j];
}

// ---------------- rel-position projections: warp-per-row ----------------
__global__ __launch_bounds__(256)
void relproj2(const float* __restrict__ Q, const float* __restrict__ pemb,
              float* __restrict__ P)
{
    __shared__ float pt[64][34];
    __shared__ float qs[8][64];
    const int tid = threadIdx.x;
    for (int i = tid; i < NPE * 64; i += 256) {
        int j = i >> 6, d = i & 63;
        pt[d][j] = pemb[i];
    }
    __syncthreads();
    const int wid = tid >> 5, l = tid & 31;
    const size_t row = (size_t)blockIdx.x * 8 + wid;
    qs[wid][l]      = Q[row * 64 + l];
    qs[wid][l + 32] = Q[row * 64 + 32 + l];
    __syncwarp();
    float acc = 0.f, acc32 = 0.f;
    #pragma unroll
    for (int d = 0; d < 64; d++) {
        float q = qs[wid][d];
        acc   += q * pt[d][l];
        acc32 += q * pt[d][32];
    }
    P[row * NPE + l] = acc;
    if (l == 0) P[row * NPE + 32] = acc32;
}

// ---------------- row softmax over 2048 ----------------
__global__ __launch_bounds__(256)
void softmax_k(float* __restrict__ S)
{
    const size_t row = blockIdx.x;
    float4* p = reinterpret_cast<float4*>(S + row * SEQ);
    const int t = threadIdx.x;
    float4 a = p[t], b = p[t + 256];

    float m = fmaxf(fmaxf(fmaxf(a.x, a.y), fmaxf(a.z, a.w)),
                    fmaxf(fmaxf(b.x, b.y), fmaxf(b.z, b.w)));
    #pragma unroll
    for (int o = 16; o > 0; o >>= 1) m = fmaxf(m, __shfl_xor_sync(0xffffffffu, m, o));

    __shared__ float red[8];
    const int wid = t >> 5, lane = t & 31;
    if (lane == 0) red[wid] = m;
    __syncthreads();
    float gm = red[0];
    #pragma unroll
    for (int i = 1; i < 8; i++) gm = fmaxf(gm, red[i]);
    __syncthreads();

    a.x = __expf(a.x - gm); a.y = __expf(a.y - gm);
    a.z = __expf(a.z - gm); a.w = __expf(a.w - gm);
    b.x = __expf(b.x - gm); b.y = __expf(b.y - gm);
    b.z = __expf(b.z - gm); b.w = __expf(b.w - gm);

    float s = a.x + a.y + a.z + a.w + b.x + b.y + b.z + b.w;
    #pragma unroll
    for (int o = 16; o > 0; o >>= 1) s += __shfl_xor_sync(0xffffffffu, s, o);
    if (lane == 0) red[wid] = s;
    __syncthreads();
    float gs = 0.f;
    #pragma unroll
    for (int i = 0; i < 8; i++) gs += red[i];

    const float inv = 1.f / gs;
    a.x *= inv; a.y *= inv; a.z *= inv; a.w *= inv;
    b.x *= inv; b.y *= inv; b.z *= inv; b.w *= inv;
    p[t] = a; p[t + 256] = b;
}

// ---------------- launch ----------------
extern "C" void kernel_launch(void* const* d_in, const int* in_sizes, int n_in,
                              void* d_out, int out_size)
{
    const float* iQ   = (const float*)d_in[0];
    const float* iK   = (const float*)d_in[1];
    const float* iV   = (const float*)d_in[2];
    const float* Wq   = (const float*)d_in[3];
    const float* Wk   = (const float*)d_in[4];
    const float* Wv   = (const float*)d_in[5];
    const float* Wo   = (const float*)d_in[6];
    const float* pemb = (const float*)d_in[7];
    float* out = (float*)d_out;

    float *Q, *K, *P, *S, *C, *Vt, *Wt;
    cudaGetSymbolAddress((void**)&Q,  g_Q);
    cudaGetSymbolAddress((void**)&K,  g_K);
    cudaGetSymbolAddress((void**)&P,  g_P);
    cudaGetSymbolAddress((void**)&S,  g_S);
    cudaGetSymbolAddress((void**)&C,  g_C);
    cudaGetSymbolAddress((void**)&Vt, g_Vt);
    cudaGetSymbolAddress((void**)&Wt, g_Wt);

    constexpr int SM_PROJ   = 1024 + 2 * (32768 + 128 * 256);  // 132096
    constexpr int SM_SCORES = 1024 + 1 * (32768 + 128 * 256);  //  66560
    constexpr int SM_PV     = 1024 + 2 * (32768 +  64 * 256);  //  99328

    cudaFuncSetAttribute(gemm_mma<128, 2, 1>, cudaFuncAttributeMaxDynamicSharedMemorySize, SM_PROJ);
    cudaFuncSetAttribute(gemm_mma<128, 2, 4>, cudaFuncAttributeMaxDynamicSharedMemorySize, SM_PROJ);
    cudaFuncSetAttribute(gemm_mma<128, 1, 2>, cudaFuncAttributeMaxDynamicSharedMemorySize, SM_SCORES);
    cudaFuncSetAttribute(gemm_mma<64,  2, 3>, cudaFuncAttributeMaxDynamicSharedMemorySize, SM_PV);
    cudaFuncSetAttribute(gemm_mma<128, 2, 0>, cudaFuncAttributeMaxDynamicSharedMemorySize, SM_PROJ);

    // 0) transpose weights -> Wt[n][k]
    transp_w<<<dim3(DM / 32, DM / 32, 4), 256>>>(Wq, Wk, Wv, Wo, Wt);

    // 1) projections
    dim3 gproj(DM / 128, (NB * SEQ) / 128, 1);
    gemm_mma<128, 2, 1><<<gproj, 256, SM_PROJ>>>(iQ, Wt + 0 * DM * DM, Q,  nullptr, DM, 0, 0, 0);
    gemm_mma<128, 2, 1><<<gproj, 256, SM_PROJ>>>(iK, Wt + 1 * DM * DM, K,  nullptr, DM, 0, 0, 0);
    gemm_mma<128, 2, 4><<<gproj, 256, SM_PROJ>>>(iV, Wt + 2 * DM * DM, Vt, nullptr, DM, 0, 0, 0);

    // 2) rel-position projections
    relproj2<<<(BH * SEQ) / 8, 256>>>(Q, pemb, P);

    // 3) scores = (Q K^T + bias) / 8
    dim3 gsc(SEQ / 128, SEQ / 128, BH);
    gemm_mma<128, 1, 2><<<gsc, 256, SM_SCORES>>>(Q, K, S, P, AD,
        (long)SEQ * AD, (long)SEQ * AD, (long)SEQ * SEQ);

    // 4) softmax
    softmax_k<<<BH * SEQ, 256>>>(S);

    // 5) ctx = probs @ V -> [b][q][h][d]  (B = Vt rows [d][s])
    dim3 gpv(1, SEQ / 128, BH);
    gemm_mma<64, 2, 3><<<gpv, 256, SM_PV>>>(S, Vt, C, nullptr, SEQ,
        (long)SEQ * SEQ, (long)AD * SEQ, 0);

    // 6) out = ctx @ Wo
    gemm_mma<128, 2, 0><<<gproj, 256, SM_PROJ>>>(C, Wt + 3 * DM * DM, out, nullptr, DM, 0, 0, 0);
}

// round 6
// speedup vs baseline: 4.3631x; 2.6873x over previous
#include <cuda_runtime.h>
#include <cuda_bf16.h>
#include <cstdint>

#define SEQ 2048
#define NB 2
#define NH 16
#define AD 64
#define DM 1024
#define BH (NB*NH)
#define NPE 33
typedef __nv_bfloat16 bf16;

// ---------------- scratch (no allocation allowed) ----------------
__device__ bf16 g_Wth[(size_t)4*DM*DM], g_Wtl[(size_t)4*DM*DM];
__device__ bf16 g_Ih[(size_t)NB*SEQ*DM],  g_Il[(size_t)NB*SEQ*DM];
__device__ bf16 g_Qh[(size_t)BH*SEQ*AD],  g_Ql[(size_t)BH*SEQ*AD];
__device__ bf16 g_Kh[(size_t)BH*SEQ*AD],  g_Kl[(size_t)BH*SEQ*AD];
__device__ bf16 g_Vh[(size_t)BH*SEQ*AD],  g_Vl[(size_t)BH*SEQ*AD];
__device__ bf16 g_Ch[(size_t)NB*SEQ*DM],  g_Cl[(size_t)NB*SEQ*DM];
__device__ float g_P[(size_t)BH*SEQ*NPE];

// ---------------- helpers ----------------
__device__ __forceinline__ uint32_t s2u(const void* p) {
    uint32_t a;
    asm("{ .reg .u64 t; cvta.to.shared.u64 t, %1; cvt.u32.u64 %0, t; }" : "=r"(a) : "l"(p));
    return a;
}
__device__ __forceinline__ uint32_t swz(uint32_t o) { return o ^ ((o >> 3) & 0x70); }

__device__ __forceinline__ void ldsm4(uint32_t* r, uint32_t a) {
    asm volatile("ldmatrix.sync.aligned.m8n8.x4.shared.b16 {%0,%1,%2,%3}, [%4];"
                 : "=r"(r[0]), "=r"(r[1]), "=r"(r[2]), "=r"(r[3]) : "r"(a));
}
__device__ __forceinline__ void ldsm4t(uint32_t* r, uint32_t a) {
    asm volatile("ldmatrix.sync.aligned.m8n8.x4.trans.shared.b16 {%0,%1,%2,%3}, [%4];"
                 : "=r"(r[0]), "=r"(r[1]), "=r"(r[2]), "=r"(r[3]) : "r"(a));
}
__device__ __forceinline__ void mma_bf16(float* d, const uint32_t* a, const uint32_t* b) {
    asm volatile("mma.sync.aligned.m16n8k16.row.col.f32.bf16.bf16.f32 "
                 "{%0,%1,%2,%3}, {%4,%5,%6,%7}, {%8,%9}, {%0,%1,%2,%3};"
                 : "+f"(d[0]), "+f"(d[1]), "+f"(d[2]), "+f"(d[3])
                 : "r"(a[0]), "r"(a[1]), "r"(a[2]), "r"(a[3]), "r"(b[0]), "r"(b[1]));
}
#define CP16(dst, src) \
    asm volatile("cp.async.cg.shared.global [%0], [%1], 16;" :: "r"(dst), "l"(src))
#define CPCOMMIT asm volatile("cp.async.commit_group;" ::: "memory")
#define CPWAIT(n) asm volatile("cp.async.wait_group %0;" :: "n"(n) : "memory")

__device__ __forceinline__ void packhl(float x0, float x1, uint32_t& ph, uint32_t& pl) {
    bf16 h0 = __float2bfloat16(x0), h1 = __float2bfloat16(x1);
    ph = ((uint32_t)__bfloat16_as_ushort(h1) << 16) | __bfloat16_as_ushort(h0);
    float l0 = x0 - __bfloat162float(h0), l1 = x1 - __bfloat162float(h1);
    asm("cvt.rn.bf16x2.f32 %0, %1, %2;" : "=r"(pl) : "f"(l1), "f"(l0));
}
__device__ __forceinline__ void cvt_hl(float4 v, uint2& h2, uint2& l2) {
    uint32_t a, b, c, d;
    packhl(v.x, v.y, a, c);
    packhl(v.z, v.w, b, d);
    h2 = make_uint2(a, b); l2 = make_uint2(c, d);
}

// ---------------- prep kernels ----------------
__global__ __launch_bounds__(256)
void split_in(const float4* __restrict__ x, bf16* __restrict__ h, bf16* __restrict__ l)
{
    size_t i = (size_t)blockIdx.x * 256 + threadIdx.x;
    float4 v = x[i];
    uint2 h2, l2; cvt_hl(v, h2, l2);
    *reinterpret_cast<uint2*>(h + i * 4) = h2;
    *reinterpret_cast<uint2*>(l + i * 4) = l2;
}

__global__ __launch_bounds__(256)
void transp_w(const float* __restrict__ W0, const float* __restrict__ W1,
              const float* __restrict__ W2, const float* __restrict__ W3,
              bf16* __restrict__ oh, bf16* __restrict__ ol)
{
    __shared__ float t[32][33];
    const float* W = (blockIdx.z == 0) ? W0 : (blockIdx.z == 1) ? W1
                   : (blockIdx.z == 2) ? W2 : W3;
    bf16* Oh = oh + (size_t)blockIdx.z * DM * DM;
    bf16* Ol = ol + (size_t)blockIdx.z * DM * DM;
    const int tx = threadIdx.x & 31, ty = threadIdx.x >> 5;
    const int x = blockIdx.x * 32 + tx, y = blockIdx.y * 32 + ty;
    #pragma unroll
    for (int j = 0; j < 32; j += 8) t[ty + j][tx] = W[(size_t)(y + j) * DM + x];
    __syncthreads();
    const int xo = blockIdx.y * 32 + tx, yo = blockIdx.x * 32 + ty;
    #pragma unroll
    for (int j = 0; j < 32; j += 8) {
        float v = t[tx][ty + j];
        bf16 h = __float2bfloat16(v);
        Oh[(size_t)(yo + j) * DM + xo] = h;
        Ol[(size_t)(yo + j) * DM + xo] = __float2bfloat16(v - __bfloat162float(h));
    }
}

// ---------------------------------------------------------------------------
// split-bf16 GEMM, pre-split operands.  C[128,128] = A[128,K] * B[128,K]^T.
// EPI 0: fp32 [m][DM].   EPI 1: hi/lo bf16 head-major [bh][s][d].
// ---------------------------------------------------------------------------
template<int EPI>
__global__ __launch_bounds__(256, 1)
void gemm_hl(const bf16* __restrict__ Ah_g, const bf16* __restrict__ Al_g,
             const bf16* __restrict__ Bh_g, const bf16* __restrict__ Bl_g,
             float* __restrict__ Cf, bf16* __restrict__ Oh, bf16* __restrict__ Ol,
             int K)
{
    extern __shared__ char dsm[];
    const uint32_t raw = s2u(dsm);
    const uint32_t sb  = (raw + 1023u) & ~1023u;
    const int tid = threadIdx.x, wid = tid >> 5, lane = tid & 31;
    const int bm = blockIdx.y * 128, bn = blockIdx.x * 128;
    const int wm = (wid >> 1) * 32, wn = (wid & 1) * 64;

    float acc[2][8][4] = {};

    auto load_stage = [&](int buf, int k0) {
        uint32_t base = sb + (uint32_t)buf * 65536u;
        #pragma unroll
        for (int i = 0; i < 16; i++) {
            int c = tid + i * 256;
            int t_ = c >> 10, row = (c >> 3) & 127, j = c & 7;
            const bf16* src =
                (t_ == 0) ? Ah_g + (size_t)(bm + row) * K + k0 + j * 8 :
                (t_ == 1) ? Al_g + (size_t)(bm + row) * K + k0 + j * 8 :
                (t_ == 2) ? Bh_g + (size_t)(bn + row) * K + k0 + j * 8 :
                            Bl_g + (size_t)(bn + row) * K + k0 + j * 8;
            uint32_t dst = base + (uint32_t)t_ * 16384u +
                           swz((uint32_t)row * 128u + (uint32_t)j * 16u);
            CP16(dst, src);
        }
        CPCOMMIT;
    };

    const int NS = K / 64;
    load_stage(0, 0);
    for (int s = 0; s < NS; s++) {
        if (s + 1 < NS) { load_stage((s + 1) & 1, (s + 1) * 64); CPWAIT(1); }
        else           { CPWAIT(0); }
        __syncthreads();
        const uint32_t base = sb + (uint32_t)(s & 1) * 65536u;
        const uint32_t AhB = base, AlB = base + 16384u, BhB = base + 32768u, BlB = base + 49152u;
        #pragma unroll
        for (int kk = 0; kk < 4; kk++) {
            const uint32_t kB = (uint32_t)kk * 32u;
            uint32_t ah[2][4], al_[2][4];
            const uint32_t aoff = (((uint32_t)lane >> 4) << 4) + kB;
            #pragma unroll
            for (int mt = 0; mt < 2; mt++) {
                const uint32_t sw = swz((uint32_t)(wm + mt * 16 + (lane & 15)) * 128u + aoff);
                ldsm4(ah[mt], AhB + sw);
                ldsm4(al_[mt], AlB + sw);
            }
            const uint32_t boff = ((((uint32_t)lane >> 3) & 1u) << 4) + kB;
            const uint32_t brow = (uint32_t)(wn + (lane & 7) + ((lane >> 4) << 3));
            #pragma unroll
            for (int g = 0; g < 4; g++) {
                uint32_t bh4[4], bl4[4];
                const uint32_t sw = swz((brow + (uint32_t)g * 16u) * 128u + boff);
                ldsm4(bh4, BhB + sw);
                ldsm4(bl4, BlB + sw);
                #pragma unroll
                for (int mt = 0; mt < 2; mt++)
                    #pragma unroll
                    for (int q = 0; q < 2; q++) {
                        mma_bf16(acc[mt][g * 2 + q], ah[mt],  bh4 + q * 2);
                        mma_bf16(acc[mt][g * 2 + q], ah[mt],  bl4 + q * 2);
                        mma_bf16(acc[mt][g * 2 + q], al_[mt], bh4 + q * 2);
                    }
            }
        }
        __syncthreads();
    }

    #pragma unroll
    for (int mt = 0; mt < 2; mt++)
        #pragma unroll
        for (int nt = 0; nt < 8; nt++) {
            const int m = bm + wm + mt * 16 + (lane >> 2);
            const int n = bn + wn + nt * 8 + (lane & 3) * 2;
            #pragma unroll
            for (int rr = 0; rr < 2; rr++) {
                const int mm = m + rr * 8;
                const float x0 = acc[mt][nt][rr * 2 + 0], x1 = acc[mt][nt][rr * 2 + 1];
                if constexpr (EPI == 0) {
                    *reinterpret_cast<float2*>(Cf + (size_t)mm * DM + n) = make_float2(x0, x1);
                } else {
                    const int b_ = mm >> 11, s_ = mm & 2047, h_ = n >> 6, d_ = n & 63;
                    const size_t o = (((size_t)(b_ * NH + h_)) * SEQ + s_) * AD + d_;
                    uint32_t ph, pl; packhl(x0, x1, ph, pl);
                    *reinterpret_cast<uint32_t*>(Oh + o) = ph;
                    *reinterpret_cast<uint32_t*>(Ol + o) = pl;
                }
            }
        }
}

// ---------------------------------------------------------------------------
// fused flash attention: (QK^T + bias)/8 -> online softmax -> @V
// grid (SEQ/128, BH), 256 threads, warp owns 16 q-rows.
// ---------------------------------------------------------------------------
__global__ __launch_bounds__(256, 1)
void flash_attn(const bf16* __restrict__ Qh_g, const bf16* __restrict__ Ql_g,
                const bf16* __restrict__ Kh_g, const bf16* __restrict__ Kl_g,
                const bf16* __restrict__ Vh_g, const bf16* __restrict__ Vl_g,
                const float* __restrict__ Pr,
                bf16* __restrict__ Ch, bf16* __restrict__ Cl)
{
    extern __shared__ char dsm[];
    const uint32_t raw = s2u(dsm);
    const uint32_t sb  = (raw + 1023u) & ~1023u;
    char* sp = dsm + (sb - raw);
    const int tid = threadIdx.x, wid = tid >> 5, lane = tid & 31;
    const int bh = blockIdx.y, bm = blockIdx.x * 128;
    const int wm = wid * 16;

    const bf16* Qh = Qh_g + ((size_t)bh * SEQ + bm) * AD;
    const bf16* Ql = Ql_g + ((size_t)bh * SEQ + bm) * AD;
    const bf16* Kh = Kh_g + (size_t)bh * SEQ * AD;
    const bf16* Kl = Kl_g + (size_t)bh * SEQ * AD;
    const bf16* Vh = Vh_g + (size_t)bh * SEQ * AD;
    const bf16* Vl = Vl_g + (size_t)bh * SEQ * AD;

    constexpr uint32_t QOFF = 0, STG = 32768, PROW = 32768 + 2 * 65536;
    float* prow = reinterpret_cast<float*>(sp + PROW);

    auto load_stage = [&](int buf, int s0) {
        uint32_t base = sb + STG + (uint32_t)buf * 65536u;
        #pragma unroll
        for (int i = 0; i < 16; i++) {
            int c = tid + i * 256;
            int t_ = c >> 10, row = (c >> 3) & 127, j = c & 7;
            const bf16* src =
                (t_ == 0) ? Kh + (size_t)(s0 + row) * AD + j * 8 :
                (t_ == 1) ? Kl + (size_t)(s0 + row) * AD + j * 8 :
                (t_ == 2) ? Vh + (size_t)(s0 + row) * AD + j * 8 :
                            Vl + (size_t)(s0 + row) * AD + j * 8;
            uint32_t dst = base + (uint32_t)t_ * 16384u +
                           swz((uint32_t)row * 128u + (uint32_t)j * 16u);
            CP16(dst, src);
        }
        CPCOMMIT;
    };

    // Q tiles (hi/lo) + stage0 in first group
    {
        #pragma unroll
        for (int i = 0; i < 8; i++) {
            int c = tid + i * 256;
            int t_ = c >> 10, row = (c >> 3) & 127, j = c & 7;
            const bf16* src = (t_ ? Ql : Qh) + (size_t)row * AD + j * 8;
            uint32_t dst = sb + QOFF + (uint32_t)t_ * 16384u +
                           swz((uint32_t)row * 128u + (uint32_t)j * 16u);
            CP16(dst, src);
        }
    }
    load_stage(0, 0);   // commits Q + stage0 together

    for (int i = tid; i < 128 * NPE; i += 256)
        prow[i] = Pr[((size_t)bh * SEQ + bm) * NPE + i];

    float ctx[8][4] = {};
    float mrun0 = -1e30f, mrun1 = -1e30f, lrun0 = 0.f, lrun1 = 0.f;
    uint32_t qah[4][4], qal[4][4];
    float blo0 = 0.f, blo1 = 0.f, bhi0 = 0.f, bhi1 = 0.f;
    const int rl0 = wm + (lane >> 2), rl1 = rl0 + 8;

    for (int st = 0; st < 16; st++) {
        if (st + 1 < 16) { load_stage((st + 1) & 1, (st + 1) * 128); CPWAIT(1); }
        else             { CPWAIT(0); }
        __syncthreads();

        if (st == 0) {
            #pragma unroll
            for (int kk = 0; kk < 4; kk++) {
                const uint32_t aoff = (((uint32_t)lane >> 4) << 4) + (uint32_t)kk * 32u;
                const uint32_t sw = swz((uint32_t)(wm + (lane & 15)) * 128u + aoff);
                ldsm4(qah[kk], sb + QOFF + sw);
                ldsm4(qal[kk], sb + QOFF + 16384u + sw);
            }
            blo0 = prow[rl0 * NPE + 0];  bhi0 = prow[rl0 * NPE + 32];
            blo1 = prow[rl1 * NPE + 0];  bhi1 = prow[rl1 * NPE + 32];
        }

        const uint32_t base = sb + STG + (uint32_t)(st & 1) * 65536u;
        const uint32_t KhB = base, KlB = base + 16384u, VhB = base + 32768u, VlB = base + 49152u;

        // ---- S = Q K^T ----
        float tS[16][4];
        #pragma unroll
        for (int nt = 0; nt < 16; nt++)
            #pragma unroll
            for (int e = 0; e < 4; e++) tS[nt][e] = 0.f;

        #pragma unroll
        for (int kk = 0; kk < 4; kk++) {
            const uint32_t boff = ((((uint32_t)lane >> 3) & 1u) << 4) + (uint32_t)kk * 32u;
            const uint32_t brow = (uint32_t)((lane & 7) + ((lane >> 4) << 3));
            #pragma unroll
            for (int g = 0; g < 8; g++) {
                uint32_t bh4[4], bl4[4];
                const uint32_t sw = swz((brow + (uint32_t)g * 16u) * 128u + boff);
                ldsm4(bh4, KhB + sw);
                ldsm4(bl4, KlB + sw);
                #pragma unroll
                for (int q = 0; q < 2; q++) {
                    mma_bf16(tS[g * 2 + q], qah[kk], bh4 + q * 2);
                    mma_bf16(tS[g * 2 + q], qah[kk], bl4 + q * 2);
                    mma_bf16(tS[g * 2 + q], qal[kk], bh4 + q * 2);
                }
            }
        }

        // ---- bias + scale ----
        const int sbase = st * 128, qmin = bm + wm;
        if (sbase + 127 <= qmin - 16) {
            #pragma unroll
            for (int nt = 0; nt < 16; nt++)
                #pragma unroll
                for (int e = 0; e < 4; e++)
                    tS[nt][e] = (tS[nt][e] + ((e < 2) ? blo0 : blo1)) * 0.125f;
        } else if (sbase >= qmin + 31) {
            #pragma unroll
            for (int nt = 0; nt < 16; nt++)
                #pragma unroll
                for (int e = 0; e < 4; e++)
                    tS[nt][e] = (tS[nt][e] + ((e < 2) ? bhi0 : bhi1)) * 0.125f;
        } else {
            #pragma unroll
            for (int nt = 0; nt < 16; nt++)
                #pragma unroll
                for (int e = 0; e < 4; e++) {
                    const int sg = sbase + nt * 8 + (lane & 3) * 2 + (e & 1);
                    const int rl = (e < 2) ? rl0 : rl1;
                    int idx = sg - (bm + rl) + 16;
                    idx = idx < 0 ? 0 : (idx > 32 ? 32 : idx);
                    tS[nt][e] = (tS[nt][e] + prow[rl * NPE + idx]) * 0.125f;
                }
        }

        // ---- online softmax ----
        float mx0 = -1e30f, mx1 = -1e30f;
        #pragma unroll
        for (int nt = 0; nt < 16; nt++) {
            mx0 = fmaxf(mx0, fmaxf(tS[nt][0], tS[nt][1]));
            mx1 = fmaxf(mx1, fmaxf(tS[nt][2], tS[nt][3]));
        }
        mx0 = fmaxf(mx0, __shfl_xor_sync(0xffffffffu, mx0, 1));
        mx0 = fmaxf(mx0, __shfl_xor_sync(0xffffffffu, mx0, 2));
        mx1 = fmaxf(mx1, __shfl_xor_sync(0xffffffffu, mx1, 1));
        mx1 = fmaxf(mx1, __shfl_xor_sync(0xffffffffu, mx1, 2));
        const float M0 = fmaxf(mrun0, mx0), M1 = fmaxf(mrun1, mx1);
        const float a0 = __expf(mrun0 - M0), a1 = __expf(mrun1 - M1);
        mrun0 = M0; mrun1 = M1;
        float s0 = 0.f, s1 = 0.f;
        #pragma unroll
        for (int nt = 0; nt < 16; nt++) {
            tS[nt][0] = __expf(tS[nt][0] - M0); s0 += tS[nt][0];
            tS[nt][1] = __expf(tS[nt][1] - M0); s0 += tS[nt][1];
            tS[nt][2] = __expf(tS[nt][2] - M1); s1 += tS[nt][2];
            tS[nt][3] = __expf(tS[nt][3] - M1); s1 += tS[nt][3];
        }
        s0 += __shfl_xor_sync(0xffffffffu, s0, 1);
        s0 += __shfl_xor_sync(0xffffffffu, s0, 2);
        s1 += __shfl_xor_sync(0xffffffffu, s1, 1);
        s1 += __shfl_xor_sync(0xffffffffu, s1, 2);
        lrun0 = lrun0 * a0 + s0;
        lrun1 = lrun1 * a1 + s1;
        #pragma unroll
        for (int g = 0; g < 8; g++) {
            ctx[g][0] *= a0; ctx[g][1] *= a0;
            ctx[g][2] *= a1; ctx[g][3] *= a1;
        }

        // ---- ctx += P V ----
        #pragma unroll
        for (int c = 0; c < 8; c++) {
            uint32_t ph4[4], pl4[4];
            packhl(tS[2*c][0],   tS[2*c][1],   ph4[0], pl4[0]);
            packhl(tS[2*c][2],   tS[2*c][3],   ph4[1], pl4[1]);
            packhl(tS[2*c+1][0], tS[2*c+1][1], ph4[2], pl4[2]);
            packhl(tS[2*c+1][2], tS[2*c+1][3], ph4[3], pl4[3]);
            const uint32_t vrow  = (uint32_t)(c * 16 + (lane & 7) + ((lane >> 3) & 1) * 8);
            const uint32_t vcolb = (((uint32_t)lane >> 4) << 4);
            #pragma unroll
            for (int g = 0; g < 4; g++) {
                uint32_t vh4[4], vl4[4];
                const uint32_t sw = swz(vrow * 128u + vcolb + (uint32_t)g * 32u);
                ldsm4t(vh4, VhB + sw);
                ldsm4t(vl4, VlB + sw);
                #pragma unroll
                for (int q = 0; q < 2; q++) {
                    mma_bf16(ctx[g * 2 + q], ph4, vh4 + q * 2);
                    mma_bf16(ctx[g * 2 + q], ph4, vl4 + q * 2);
                    mma_bf16(ctx[g * 2 + q], pl4, vh4 + q * 2);
                }
            }
        }
        __syncthreads();
    }

    // ---- epilogue: ctx/l -> hi/lo bf16 [b][q][h*64+d] ----
    const float inv0 = 1.f / lrun0, inv1 = 1.f / lrun1;
    const int b_ = bh >> 4, h_ = bh & 15;
    const int q0 = bm + wm + (lane >> 2);
    #pragma unroll
    for (int g = 0; g < 8; g++) {
        const int col = h_ * 64 + g * 8 + (lane & 3) * 2;
        #pragma unroll
        for (int rr = 0; rr < 2; rr++) {
            const int q = q0 + rr * 8;
            const float inv = rr ? inv1 : inv0;
            const float x0 = ctx[g][rr * 2 + 0] * inv, x1 = ctx[g][rr * 2 + 1] * inv;
            uint32_t ph, pl; packhl(x0, x1, ph, pl);
            const size_t o = ((size_t)b_ * SEQ + q) * DM + col;
            *reinterpret_cast<uint32_t*>(Ch + o) = ph;
            *reinterpret_cast<uint32_t*>(Cl + o) = pl;
        }
    }
}

// ---------------- rel-position projections ----------------
__global__ __launch_bounds__(256)
void relproj2(const bf16* __restrict__ Qh, const bf16* __restrict__ Ql,
              const float* __restrict__ pemb, float* __restrict__ P)
{
    __shared__ float pt[64][34];
    __shared__ float qs[8][64];
    const int tid = threadIdx.x;
    for (int i = tid; i < NPE * 64; i += 256) {
        int j = i >> 6, d = i & 63;
        pt[d][j] = pemb[i];
    }
    __syncthreads();
    const int wid = tid >> 5, l = tid & 31;
    const size_t row = (size_t)blockIdx.x * 8 + wid;
    qs[wid][l]      = __bfloat162float(Qh[row * 64 + l])      + __bfloat162float(Ql[row * 64 + l]);
    qs[wid][l + 32] = __bfloat162float(Qh[row * 64 + 32 + l]) + __bfloat162float(Ql[row * 64 + 32 + l]);
    __syncwarp();
    float acc = 0.f, acc32 = 0.f;
    #pragma unroll
    for (int d = 0; d < 64; d++) {
        float q = qs[wid][d];
        acc   += q * pt[d][l];
        acc32 += q * pt[d][32];
    }
    P[row * NPE + l] = acc;
    if (l == 0) P[row * NPE + 32] = acc32;
}

// ---------------- launch ----------------
extern "C" void kernel_launch(void* const* d_in, const int* in_sizes, int n_in,
                              void* d_out, int out_size)
{
    const float* iQ   = (const float*)d_in[0];
    const float* iK   = (const float*)d_in[1];
    const float* iV   = (const float*)d_in[2];
    const float* Wq   = (const float*)d_in[3];
    const float* Wk   = (const float*)d_in[4];
    const float* Wv   = (const float*)d_in[5];
    const float* Wo   = (const float*)d_in[6];
    const float* pemb = (const float*)d_in[7];
    float* out = (float*)d_out;

    bf16 *Wth, *Wtl, *Ih, *Il, *Qh, *Ql, *Kh, *Kl, *Vh, *Vl, *Ch, *Cl;
    float* P;
    cudaGetSymbolAddress((void**)&Wth, g_Wth);
    cudaGetSymbolAddress((void**)&Wtl, g_Wtl);
    cudaGetSymbolAddress((void**)&Ih,  g_Ih);
    cudaGetSymbolAddress((void**)&Il,  g_Il);
    cudaGetSymbolAddress((void**)&Qh,  g_Qh);
    cudaGetSymbolAddress((void**)&Ql,  g_Ql);
    cudaGetSymbolAddress((void**)&Kh,  g_Kh);
    cudaGetSymbolAddress((void**)&Kl,  g_Kl);
    cudaGetSymbolAddress((void**)&Vh,  g_Vh);
    cudaGetSymbolAddress((void**)&Vl,  g_Vl);
    cudaGetSymbolAddress((void**)&Ch,  g_Ch);
    cudaGetSymbolAddress((void**)&Cl,  g_Cl);
    cudaGetSymbolAddress((void**)&P,   g_P);

    constexpr int SM_GEMM  = 1024 + 2 * 65536;            // 132096
    constexpr int SM_FLASH = 1024 + 32768 + 2 * 65536 + 128 * NPE * 4; // 181760
    cudaFuncSetAttribute(gemm_hl<0>, cudaFuncAttributeMaxDynamicSharedMemorySize, SM_GEMM);
    cudaFuncSetAttribute(gemm_hl<1>, cudaFuncAttributeMaxDynamicSharedMemorySize, SM_GEMM);
    cudaFuncSetAttribute(flash_attn, cudaFuncAttributeMaxDynamicSharedMemorySize, SM_FLASH);

    const int NELEM4 = NB * SEQ * DM / 4;   // float4 count per input

    // 0) prep: transpose+split weights
    transp_w<<<dim3(DM / 32, DM / 32, 4), 256>>>(Wq, Wk, Wv, Wo, Wth, Wtl);

    // 1) projections (input split reused serially)
    dim3 gp(8, 32);
    split_in<<<NELEM4 / 256, 256>>>((const float4*)iQ, Ih, Il);
    gemm_hl<1><<<gp, 256, SM_GEMM>>>(Ih, Il, Wth, Wtl, nullptr, Qh, Ql, DM);
    split_in<<<NELEM4 / 256, 256>>>((const float4*)iK, Ih, Il);
    gemm_hl<1><<<gp, 256, SM_GEMM>>>(Ih, Il, Wth + (size_t)DM * DM, Wtl + (size_t)DM * DM,
                                     nullptr, Kh, Kl, DM);
    split_in<<<NELEM4 / 256, 256>>>((const float4*)iV, Ih, Il);
    gemm_hl<1><<<gp, 256, SM_GEMM>>>(Ih, Il, Wth + (size_t)2 * DM * DM, Wtl + (size_t)2 * DM * DM,
                                     nullptr, Vh, Vl, DM);

    // 2) rel-position projections
    relproj2<<<(BH * SEQ) / 8, 256>>>(Qh, Ql, pemb, P);

    // 3) fused attention -> ctx hi/lo
    flash_attn<<<dim3(SEQ / 128, BH), 256, SM_FLASH>>>(Qh, Ql, Kh, Kl, Vh, Vl, P, Ch, Cl);

    // 4) out = ctx @ Wo
    gemm_hl<0><<<gp, 256, SM_GEMM>>>(Ch, Cl, Wth + (size_t)3 * DM * DM, Wtl + (size_t)3 * DM * DM,
                                     out, nullptr, nullptr, DM);
}